// round 6
// baseline (speedup 1.0000x reference)
#include <cuda_runtime.h>
#include <cuda_bf16.h>
#include <cstdint>

namespace {
constexpr int Bn = 4096;   // batch
constexpr int Tn = 32;     // theta size
constexpr int Xn = 256;    // x size
constexpr int En = 32;     // experts
constexpr int Hn = 512;    // hidden
constexpr int Ln = 2;      // hidden layers
constexpr int BM = 64;     // rows per CTA
constexpr int BK = 16;     // K per chunk
constexpr int NT = 512;    // threads (16 warps: 2 x 8)
constexpr int ST = 3;      // TMA ring stages
constexpr int CHUNK_F = BK * Hn;            // 8192 floats, B-frag packed
constexpr int CHUNK_BYTES = CHUNK_F * 4;    // 32768
constexpr int HBF_F = BM * Hn;              // 32768 floats, A-frag packed
constexpr int SMEM_BYTES = (HBF_F + ST * CHUNK_F) * 4;   // 229376
constexpr int CPE = (Tn + Xn) / BK + Ln * (Hn / BK);     // 18 + 64 = 82 chunks/expert
}

// Weights, tf32-pre-rounded, per-expert flattened chunk stream in
// B-fragment-packed order: chunk float f -> (s=f>>12, col=(f&4095)>>3,
// t=(f&7)>>1, half=f&1), source row kr = s*8 + half*4 + t.
__device__ float wscratch[(size_t)En * CPE * CHUNK_F];

__device__ __forceinline__ uint32_t tf32r(float f) {
    uint32_t r;
    asm("cvt.rna.tf32.f32 %0, %1;" : "=r"(r) : "f"(f));
    return r;
}

// A-fragment-packed activation index for element (row r, col c):
// block (k8 = c>>3, mt16 = r>>4), lane = (r&7)*4 + (c&3),
// component = ((r>>3)&1) + 2*((c>>2)&1)
__device__ __forceinline__ int aidx(int r, int c) {
    return (((c >> 3) * 4 + (r >> 4)) * 32 + (r & 7) * 4 + (c & 3)) * 4
           + ((r >> 3) & 1) + 2 * ((c >> 2) & 1);
}

__device__ __forceinline__ void mma_tf32(float c[4],
                                         uint32_t a0, uint32_t a1, uint32_t a2, uint32_t a3,
                                         uint32_t b0, uint32_t b1) {
    asm volatile(
        "mma.sync.aligned.m16n8k8.row.col.f32.tf32.tf32.f32 "
        "{%0,%1,%2,%3}, {%4,%5,%6,%7}, {%8,%9}, {%0,%1,%2,%3};\n"
        : "+f"(c[0]), "+f"(c[1]), "+f"(c[2]), "+f"(c[3])
        : "r"(a0), "r"(a1), "r"(a2), "r"(a3), "r"(b0), "r"(b1));
}

__device__ __forceinline__ void mbar_init(uint32_t mbar, uint32_t cnt) {
    asm volatile("mbarrier.init.shared.b64 [%0], %1;" :: "r"(mbar), "r"(cnt) : "memory");
}
__device__ __forceinline__ void mbar_expect_tx(uint32_t mbar, uint32_t bytes) {
    asm volatile("mbarrier.arrive.expect_tx.shared.b64 _, [%0], %1;"
                 :: "r"(mbar), "r"(bytes) : "memory");
}
__device__ __forceinline__ void bulk_g2s(uint32_t dst, const void* src,
                                         uint32_t bytes, uint32_t mbar) {
    asm volatile(
        "cp.async.bulk.shared::cta.global.mbarrier::complete_tx::bytes "
        "[%0], [%1], %2, [%3];"
        :: "r"(dst), "l"(src), "r"(bytes), "r"(mbar) : "memory");
}
__device__ __forceinline__ void mbar_wait(uint32_t mbar, uint32_t phase) {
    uint32_t done;
    do {
        asm volatile(
            "{\n\t.reg .pred p;\n\t"
            "mbarrier.try_wait.parity.acquire.cta.shared::cta.b64 p, [%1], %2, 0x989680;\n\t"
            "selp.b32 %0, 1, 0, p;\n\t}"
            : "=r"(done) : "r"(mbar), "r"(phase) : "memory");
    } while (!done);
}

// ---------- prep: tf32-round weights into B-frag-packed chunk stream --------
__global__ void mnre_prep(const float* __restrict__ W1t, const float* __restrict__ W1x,
                          const float* __restrict__ Wh) {
    const int blk = blockIdx.x;              // e*CPE + cg
    const int e  = blk / CPE;
    const int cg = blk % CPE;
    float* dst = wscratch + (size_t)blk * CHUNK_F;
    for (int f = threadIdx.x; f < CHUNK_F; f += blockDim.x) {
        const int s    = f >> 12;
        const int rem  = f & 4095;
        const int col  = rem >> 3;
        const int q    = rem & 7;
        const int t    = q >> 1;
        const int half = q & 1;
        const int kr   = s * 8 + half * 4 + t;
        const float* src;
        if (cg < 18) {
            const int k = cg * 16 + kr;
            src = (k < Tn) ? (W1t + (size_t)(e * Tn + k) * Hn)
                           : (W1x + (size_t)(e * Xn + (k - Tn)) * Hn);
        } else if (cg < 50) {
            const int k = (cg - 18) * 16 + kr;
            src = Wh + ((size_t)(0 * En + e) * Hn + k) * Hn;
        } else {
            const int k = (cg - 50) * 16 + kr;
            src = Wh + ((size_t)(1 * En + e) * Hn + k) * Hn;
        }
        dst[f] = __uint_as_float(tf32r(src[col]));
    }
}

// ---------- main fused kernel ------------------------------------------------
__global__ __launch_bounds__(NT, 1)
void mnre_tf32f(const float* __restrict__ theta, const float* __restrict__ x,
                const int*   __restrict__ masks,
                const float* __restrict__ b1,  const float* __restrict__ a1,
                const float* __restrict__ bh,  const float* __restrict__ ah,
                const float* __restrict__ Wo,  const float* __restrict__ bo,
                float* __restrict__ out)
{
    extern __shared__ float smem[];
    float* hbf = smem;                 // A-frag-packed activations [HBF_F]
    float* wrg = smem + HBF_F;         // ST x CHUNK_F weight ring
    __shared__ alignas(8) unsigned long long mbars[ST];

    const int e    = blockIdx.y;
    const int m0   = blockIdx.x * BM;
    const int tid  = threadIdx.x;
    const int lane = tid & 31;
    const int wy   = tid >> 5;         // 0..15
    const int warpM = wy >> 3;         // 0..1
    const int warpN = wy & 7;          // 0..7
    const int g    = lane >> 2;        // 0..7
    const int t    = lane & 3;         // 0..3
    const int nbase = warpN * 64;
    const int mbase = warpM * 32;

    uint32_t bars[ST];
    #pragma unroll
    for (int i = 0; i < ST; i++)
        bars[i] = (uint32_t)__cvta_generic_to_shared(&mbars[i]);
    const float* wexp = wscratch + (size_t)e * CPE * CHUNK_F;
    const uint32_t wrg0 = (uint32_t)__cvta_generic_to_shared(wrg);

    if (tid == 0) {
        #pragma unroll
        for (int i = 0; i < ST; i++) mbar_init(bars[i], 1);
        asm volatile("fence.proxy.async.shared::cta;" ::: "memory");
    }
    __syncthreads();

    // prologue: chunks 0..ST-2 in flight
    if (tid == 0) {
        #pragma unroll
        for (int i = 0; i < ST - 1; i++) {
            mbar_expect_tx(bars[i], CHUNK_BYTES);
            bulk_g2s(wrg0 + i * CHUNK_BYTES, wexp + (size_t)i * CHUNK_F,
                     CHUNK_BYTES, bars[i]);
        }
    }

    // ---- stage inputs into A-frag-packed hbf
    #pragma unroll
    for (int it = 0; it < (BM * Tn) / NT; it++) {
        const int i = tid + it * NT;
        const int m = i >> 5, k = i & 31;
        const float v = theta[(size_t)(m0 + m) * Tn + k] * (float)masks[e * Tn + k];
        hbf[aidx(m, k)] = __uint_as_float(tf32r(v));
    }
    #pragma unroll 4
    for (int it = 0; it < (BM * Xn) / NT; it++) {
        const int i = tid + it * NT;
        const int m = i >> 8, k = i & 255;
        hbf[aidx(m, Tn + k)] = __uint_as_float(tf32r(x[(size_t)(m0 + m) * Xn + k]));
    }

    float c[2][8][4];   // [mtile][nblock][frag]
    int qg = 0;         // global chunk index 0..CPE-1

    for (int layer = 0; layer < 1 + Ln; layer++) {
        const int K   = (layer == 0) ? (Tn + Xn) : Hn;
        const int nch = K / BK;
        const float* bias;
        const float* slope;
        if (layer == 0) {
            bias  = b1 + (size_t)e * Hn;
            slope = a1 + (size_t)e * Hn;
        } else {
            const int l = layer - 1;
            bias  = bh + (size_t)(l * En + e) * Hn;
            slope = ah + (size_t)(l * En + e) * Hn;
        }

        // init accumulators with bias
        #pragma unroll
        for (int nb = 0; nb < 8; nb++) {
            const int col0 = nbase + nb * 8 + 2 * t;
            const float bv0 = bias[col0], bv1 = bias[col0 + 1];
            #pragma unroll
            for (int mt = 0; mt < 2; mt++) {
                c[mt][nb][0] = bv0; c[mt][nb][1] = bv1;
                c[mt][nb][2] = bv0; c[mt][nb][3] = bv1;
            }
        }

        for (int ci = 0; ci < nch; ci++, qg++) {
            __syncthreads();   // everyone done with stage (qg+2)%ST's old data

            // continuous prefetch across layer boundaries
            if (tid == 0 && qg + ST - 1 < CPE) {
                const int sn = (qg + ST - 1) % ST;
                mbar_expect_tx(bars[sn], CHUNK_BYTES);
                bulk_g2s(wrg0 + sn * CHUNK_BYTES,
                         wexp + (size_t)(qg + ST - 1) * CHUNK_F,
                         CHUNK_BYTES, bars[sn]);
            }

            const int sc = qg % ST;
            mbar_wait(bars[sc], (qg / ST) & 1u);
            const float* w = wrg + sc * CHUNK_F;

            #pragma unroll
            for (int s = 0; s < 2; s++) {
                const int k8 = ci * 2 + s;
                // A frags: one LDS.128 per m16 tile
                uint32_t a[2][4];
                #pragma unroll
                for (int mt = 0; mt < 2; mt++) {
                    const float4 av = *reinterpret_cast<const float4*>(
                        hbf + ((k8 * 4 + warpM * 2 + mt) * 32 + lane) * 4);
                    a[mt][0] = __float_as_uint(av.x);
                    a[mt][1] = __float_as_uint(av.y);
                    a[mt][2] = __float_as_uint(av.z);
                    a[mt][3] = __float_as_uint(av.w);
                }
                // B frags: one LDS.64 per nb
                #pragma unroll
                for (int nb = 0; nb < 8; nb++) {
                    const int col = nbase + nb * 8 + g;
                    const float2 bv = *reinterpret_cast<const float2*>(
                        w + (s * 512 + col) * 8 + t * 2);
                    const uint32_t b0 = __float_as_uint(bv.x);
                    const uint32_t b1 = __float_as_uint(bv.y);
                    mma_tf32(c[0][nb], a[0][0], a[0][1], a[0][2], a[0][3], b0, b1);
                    mma_tf32(c[1][nb], a[1][0], a[1][1], a[1][2], a[1][3], b0, b1);
                }
            }
        }

        __syncthreads();   // all hbf reads for this layer done
        // epilogue: PReLU, tf32-round, write A-frag-packed
        #pragma unroll
        for (int nb = 0; nb < 8; nb++) {
            const int col0 = nbase + nb * 8 + 2 * t;
            const float s0 = slope[col0], s1 = slope[col0 + 1];
            const int k8  = warpN * 8 + nb;
            const int chi = t >> 1;
            const int t0  = (2 * t) & 3;
            #pragma unroll
            for (int mt = 0; mt < 2; mt++) {
                const int base = ((k8 * 4 + warpM * 2 + mt) * 32) * 4;
                float v0 = c[mt][nb][0]; v0 = (v0 >= 0.f) ? v0 : s0 * v0;
                float v1 = c[mt][nb][1]; v1 = (v1 >= 0.f) ? v1 : s1 * v1;
                float v2 = c[mt][nb][2]; v2 = (v2 >= 0.f) ? v2 : s0 * v2;
                float v3 = c[mt][nb][3]; v3 = (v3 >= 0.f) ? v3 : s1 * v3;
                float2 p0, p1;
                p0.x = __uint_as_float(tf32r(v0));   // (r_lo, c0) comp 2chi
                p0.y = __uint_as_float(tf32r(v2));   // (r_hi, c0) comp 2chi+1
                p1.x = __uint_as_float(tf32r(v1));
                p1.y = __uint_as_float(tf32r(v3));
                *reinterpret_cast<float2*>(hbf + base + (g * 4 + t0) * 4 + 2 * chi)     = p0;
                *reinterpret_cast<float2*>(hbf + base + (g * 4 + t0 + 1) * 4 + 2 * chi) = p1;
            }
        }
    }
    __syncthreads();

    // ---- output: dot with Wo, shfl reduce (fp32)
    {
        const float* wo = Wo + (size_t)e * Hn;
        const int r0 = wy * 4;   // 16 warps x 4 rows = 64
        float partial[4] = {0.f, 0.f, 0.f, 0.f};
        #pragma unroll
        for (int j = 0; j < 16; j++) {
            const int cidx = lane + j * 32;
            const float wv = wo[cidx];
            #pragma unroll
            for (int r = 0; r < 4; r++)
                partial[r] = fmaf(hbf[aidx(r0 + r, cidx)], wv, partial[r]);
        }
        const float bov = bo[e];
        #pragma unroll
        for (int r = 0; r < 4; r++) {
            float s = partial[r];
            #pragma unroll
            for (int off = 16; off > 0; off >>= 1)
                s += __shfl_xor_sync(0xffffffffu, s, off);
            if (lane == 0)
                out[(size_t)(m0 + r0 + r) * En + e] = s + bov;
        }
    }
}

extern "C" void kernel_launch(void* const* d_in, const int* in_sizes, int n_in,
                              void* d_out, int out_size) {
    const float* theta = (const float*)d_in[0];
    const float* x     = (const float*)d_in[1];
    const int*   masks = (const int*)  d_in[2];
    const float* W1t   = (const float*)d_in[3];
    const float* W1x   = (const float*)d_in[4];
    const float* b1    = (const float*)d_in[5];
    const float* a1    = (const float*)d_in[6];
    const float* Wh    = (const float*)d_in[7];
    const float* bh    = (const float*)d_in[8];
    const float* ah    = (const float*)d_in[9];
    const float* Wo    = (const float*)d_in[10];
    const float* bo    = (const float*)d_in[11];
    float* out = (float*)d_out;

    // 1) pre-round + repack weights into the fragment-packed chunk stream
    mnre_prep<<<En * CPE, 256>>>(W1t, W1x, Wh);

    // 2) fused MLP
    cudaFuncSetAttribute(mnre_tf32f, cudaFuncAttributeMaxDynamicSharedMemorySize,
                         SMEM_BYTES);
    dim3 grid(Bn / BM, En);   // 64 x 32 = 2048 CTAs
    mnre_tf32f<<<grid, NT, SMEM_BYTES>>>(theta, x, masks, b1, a1,
                                         bh, ah, Wo, bo, out);
}